// round 15
// baseline (speedup 1.0000x reference)
#include <cuda_runtime.h>
#include <cstdint>

// Problem constants
#define B_   16
#define NQ_  512
#define NK_  1024
#define CQ_  128
#define H_   8
#define D_   64
#define HD_  512   // H_*D_

// Scratch (device globals: no allocation in kernel_launch)
__device__ float g_Q[B_ * NQ_ * HD_];   // 16 MB
__device__ float g_K[B_ * NK_ * HD_];   // 32 MB (compacted rows 0..cnt)
__device__ float g_V[B_ * NK_ * HD_];   // 32 MB (compacted rows 0..cnt)
__device__ int   g_idx[B_ * NK_];       // compacted key indices per batch
__device__ int   g_cnt[B_];             // valid-key count per batch

// ---------------------------------------------------------------------------
// Packed f32x2 helpers (sm_103a)
// ---------------------------------------------------------------------------
__device__ __forceinline__ uint64_t dup2(float x) {
    uint64_t r; uint32_t u = __float_as_uint(x);
    asm("mov.b64 %0, {%1, %1};" : "=l"(r) : "r"(u));
    return r;
}
__device__ __forceinline__ void unpack2(uint64_t v, float& lo, float& hi) {
    uint32_t a, b;
    asm("mov.b64 {%0, %1}, %2;" : "=r"(a), "=r"(b) : "l"(v));
    lo = __uint_as_float(a); hi = __uint_as_float(b);
}
__device__ __forceinline__ uint64_t ffma2(uint64_t a, uint64_t b, uint64_t c) {
    uint64_t d;
    asm("fma.rn.f32x2 %0, %1, %2, %3;" : "=l"(d) : "l"(a), "l"(b), "l"(c));
    return d;
}

// ---------------------------------------------------------------------------
// Mask compaction: one block per batch, order-preserving scan.
// ---------------------------------------------------------------------------
__global__ __launch_bounds__(256) void compact_mask(
    const float* __restrict__ cmask, int* __restrict__ idx, int* __restrict__ cnt)
{
    __shared__ int warpsum[8];
    const int b = blockIdx.x;
    const int t = threadIdx.x;
    const float* m = cmask + (size_t)b * NK_;

    int v[4]; int s = 0;
#pragma unroll
    for (int j = 0; j < 4; j++) { v[j] = (m[t * 4 + j] > 0.5f) ? 1 : 0; s += v[j]; }

    const int lane = t & 31, w = t >> 5;
    int ss = s;
#pragma unroll
    for (int off = 1; off < 32; off <<= 1) {
        int n = __shfl_up_sync(0xffffffffu, ss, off);
        if (lane >= off) ss += n;
    }
    if (lane == 31) warpsum[w] = ss;
    __syncthreads();
    int wbase = 0;
#pragma unroll
    for (int i = 0; i < 8; i++) wbase += (i < w) ? warpsum[i] : 0;

    int base = wbase + ss - s;
#pragma unroll
    for (int j = 0; j < 4; j++)
        if (v[j]) idx[(size_t)b * NK_ + base++] = t * 4 + j;
    if (t == 255) cnt[b] = wbase + ss;
}

// ---------------------------------------------------------------------------
// Q projection GEMM: Y[M,512] = X[M,128] @ W[128,512] + bias (f32x2 core)
// ---------------------------------------------------------------------------
__global__ __launch_bounds__(256) void proj_gemm(
    const float* __restrict__ X, const float* __restrict__ W,
    const float* __restrict__ bias, float* __restrict__ Y)
{
    __shared__ float As[32 * 132];
    __shared__ float Bs[32 * 68];

    const int tid = threadIdx.x;
    const int tx = tid & 15;
    const int ty = tid >> 4;
    const int m0 = blockIdx.x * 128;
    const int n0 = blockIdx.y * 64;

    uint64_t acc2[4][4];
#pragma unroll
    for (int ip = 0; ip < 4; ip++)
#pragma unroll
        for (int j = 0; j < 4; j++) acc2[ip][j] = 0ull;

    for (int kc = 0; kc < 128; kc += 32) {
        __syncthreads();
#pragma unroll
        for (int r = 0; r < 4; r++) {
            int v = tid + r * 256;
            int row = v >> 3;
            int k4 = (v & 7) << 2;
            float4 x = *(const float4*)(X + (size_t)(m0 + row) * 128 + kc + k4);
            As[(k4 + 0) * 132 + row] = x.x;
            As[(k4 + 1) * 132 + row] = x.y;
            As[(k4 + 2) * 132 + row] = x.z;
            As[(k4 + 3) * 132 + row] = x.w;
        }
#pragma unroll
        for (int r = 0; r < 2; r++) {
            int v = tid + r * 256;
            int wrow = v >> 4;
            int n4 = (v & 15) << 2;
            *(float4*)(&Bs[wrow * 68 + n4]) =
                *(const float4*)(W + (size_t)(kc + wrow) * 512 + n0 + n4);
        }
        __syncthreads();

#pragma unroll 8
        for (int kk = 0; kk < 32; kk++) {
            const ulonglong2* ap = (const ulonglong2*)(&As[kk * 132 + ty * 8]);
            ulonglong2 A0 = ap[0], A1 = ap[1];
            uint64_t a2[4] = {A0.x, A0.y, A1.x, A1.y};
            float4 b0 = *(const float4*)(&Bs[kk * 68 + tx * 4]);
            uint64_t bd[4] = {dup2(b0.x), dup2(b0.y), dup2(b0.z), dup2(b0.w)};
#pragma unroll
            for (int ip = 0; ip < 4; ip++)
#pragma unroll
                for (int j = 0; j < 4; j++)
                    acc2[ip][j] = ffma2(a2[ip], bd[j], acc2[ip][j]);
        }
    }

    float4 bz = *(const float4*)(bias + n0 + tx * 4);
#pragma unroll
    for (int ip = 0; ip < 4; ip++) {
        float lo[4], hi[4];
#pragma unroll
        for (int j = 0; j < 4; j++) unpack2(acc2[ip][j], lo[j], hi[j]);
        *(float4*)(Y + (size_t)(m0 + ty * 8 + 2 * ip) * 512 + n0 + tx * 4) =
            make_float4(lo[0] + bz.x, lo[1] + bz.y, lo[2] + bz.z, lo[3] + bz.w);
        *(float4*)(Y + (size_t)(m0 + ty * 8 + 2 * ip + 1) * 512 + n0 + tx * 4) =
            make_float4(hi[0] + bz.x, hi[1] + bz.y, hi[2] + bz.z, hi[3] + bz.w);
    }
}

// ---------------------------------------------------------------------------
// Fused K+V projection over COMPACTED keys only (gather X rows by idx).
// ---------------------------------------------------------------------------
__global__ __launch_bounds__(256) void proj_kv(
    const float* __restrict__ X,
    const float* __restrict__ Wk, const float* __restrict__ bk,
    const float* __restrict__ Wv, const float* __restrict__ bv,
    const int* __restrict__ idx, const int* __restrict__ cnt,
    float* __restrict__ Yk, float* __restrict__ Yv)
{
    const int b  = blockIdx.x >> 3;          // 8 tiles per batch
    const int t0 = (blockIdx.x & 7) * 128;   // local row base within batch
    const int cnt_b = cnt[b];
    if (t0 >= cnt_b) return;                 // uniform early exit

    __shared__ float As[32 * 132];
    __shared__ float Bks[32 * 68];
    __shared__ float Bvs[32 * 68];

    const int tid = threadIdx.x;
    const int tx = tid & 15;
    const int ty = tid >> 4;
    const int n0 = blockIdx.y * 64;
    const int* Ib = idx + (size_t)b * NK_;

    uint64_t ak[4][4], av[4][4];
#pragma unroll
    for (int ip = 0; ip < 4; ip++)
#pragma unroll
        for (int j = 0; j < 4; j++) { ak[ip][j] = 0ull; av[ip][j] = 0ull; }

    for (int kc = 0; kc < 128; kc += 32) {
        __syncthreads();
#pragma unroll
        for (int r = 0; r < 4; r++) {
            int v = tid + r * 256;
            int row = v >> 3;
            int k4 = (v & 7) << 2;
            int local = t0 + row;
            int gi = Ib[local < cnt_b ? local : cnt_b - 1];
            float4 x = *(const float4*)(X + ((size_t)b * NK_ + gi) * 128 + kc + k4);
            As[(k4 + 0) * 132 + row] = x.x;
            As[(k4 + 1) * 132 + row] = x.y;
            As[(k4 + 2) * 132 + row] = x.z;
            As[(k4 + 3) * 132 + row] = x.w;
        }
#pragma unroll
        for (int r = 0; r < 2; r++) {
            int v = tid + r * 256;
            int wrow = v >> 4;
            int n4 = (v & 15) << 2;
            *(float4*)(&Bks[wrow * 68 + n4]) =
                *(const float4*)(Wk + (size_t)(kc + wrow) * 512 + n0 + n4);
            *(float4*)(&Bvs[wrow * 68 + n4]) =
                *(const float4*)(Wv + (size_t)(kc + wrow) * 512 + n0 + n4);
        }
        __syncthreads();

#pragma unroll 4
        for (int kk = 0; kk < 32; kk++) {
            const ulonglong2* ap = (const ulonglong2*)(&As[kk * 132 + ty * 8]);
            ulonglong2 A0 = ap[0], A1 = ap[1];
            uint64_t a2[4] = {A0.x, A0.y, A1.x, A1.y};
            float4 b0 = *(const float4*)(&Bks[kk * 68 + tx * 4]);
            float4 b1 = *(const float4*)(&Bvs[kk * 68 + tx * 4]);
            uint64_t bdk[4] = {dup2(b0.x), dup2(b0.y), dup2(b0.z), dup2(b0.w)};
            uint64_t bdv[4] = {dup2(b1.x), dup2(b1.y), dup2(b1.z), dup2(b1.w)};
#pragma unroll
            for (int ip = 0; ip < 4; ip++)
#pragma unroll
                for (int j = 0; j < 4; j++) {
                    ak[ip][j] = ffma2(a2[ip], bdk[j], ak[ip][j]);
                    av[ip][j] = ffma2(a2[ip], bdv[j], av[ip][j]);
                }
        }
    }

    const size_t obase = ((size_t)b * NK_ + t0);
    float4 bzk = *(const float4*)(bk + n0 + tx * 4);
    float4 bzv = *(const float4*)(bv + n0 + tx * 4);
#pragma unroll
    for (int ip = 0; ip < 4; ip++) {
        float lo[4], hi[4];
#pragma unroll
        for (int j = 0; j < 4; j++) unpack2(ak[ip][j], lo[j], hi[j]);
        *(float4*)(Yk + (obase + ty * 8 + 2 * ip) * 512 + n0 + tx * 4) =
            make_float4(lo[0] + bzk.x, lo[1] + bzk.y, lo[2] + bzk.z, lo[3] + bzk.w);
        *(float4*)(Yk + (obase + ty * 8 + 2 * ip + 1) * 512 + n0 + tx * 4) =
            make_float4(hi[0] + bzk.x, hi[1] + bzk.y, hi[2] + bzk.z, hi[3] + bzk.w);
#pragma unroll
        for (int j = 0; j < 4; j++) unpack2(av[ip][j], lo[j], hi[j]);
        *(float4*)(Yv + (obase + ty * 8 + 2 * ip) * 512 + n0 + tx * 4) =
            make_float4(lo[0] + bzv.x, lo[1] + bzv.y, lo[2] + bzv.z, lo[3] + bzv.w);
        *(float4*)(Yv + (obase + ty * 8 + 2 * ip + 1) * 512 + n0 + tx * 4) =
            make_float4(hi[0] + bzv.x, hi[1] + bzv.y, hi[2] + bzv.z, hi[3] + bzv.w);
    }
}

// ---------------------------------------------------------------------------
// Fused flash attention over pre-compacted K/V.
// GEMM1 B-operand loads vectorized (LDS.64 per 2 d-steps, halves B wavefronts);
// Ps stores vectorized to STS.128. Strided key columns (k = tx + 16j) keep all
// smem access patterns at <=2-way. Fixed-max softmax; pad slots contribute 0.
// ---------------------------------------------------------------------------
#define SQ 132
#define SK 68
#define ATTN_SMEM_BYTES ((128 * SQ + 64 * SK) * 4)

__global__ __launch_bounds__(256, 2) void attn_kernel(
    const float* __restrict__ Q, const float* __restrict__ K,
    const float* __restrict__ V, const int* __restrict__ cnt,
    float* __restrict__ Out)
{
    extern __shared__ float sm[];
    float* Qt   = sm;                    // [64 d][SQ] transposed, pre-scaled
    float* KsPs = sm + 64 * SQ;          // Ks [64 k][SK] natural <-> Ps [64 k][SQ]
    float* Vs   = sm + 128 * SQ;         // [64 k][SK] natural

    const int tid = threadIdx.x;
    const int tx = tid & 15;
    const int ty = tid >> 4;
    const int q0 = blockIdx.x * 128;
    const int h  = blockIdx.y;
    const int b  = blockIdx.z;

    const float* Qbase = Q + ((size_t)b * NQ_ + q0) * HD_ + h * D_;
    const float* Kbase = K + (size_t)b * NK_ * HD_ + h * D_;
    const float* Vbase = V + (size_t)b * NK_ * HD_ + h * D_;
    const int cnt_b = cnt[b];

    // Q tile 128x64, transposed, scaled by 1/8
#pragma unroll
    for (int r = 0; r < 8; r++) {
        int v = tid + r * 256;
        int row = v >> 4;
        int d4 = (v & 15) << 2;
        float4 x = *(const float4*)(Qbase + (size_t)row * HD_ + d4);
        Qt[(d4 + 0) * SQ + row] = x.x * 0.125f;
        Qt[(d4 + 1) * SQ + row] = x.y * 0.125f;
        Qt[(d4 + 2) * SQ + row] = x.z * 0.125f;
        Qt[(d4 + 3) * SQ + row] = x.w * 0.125f;
    }

    float l_i[8];
    uint64_t o2[4][4];
#pragma unroll
    for (int i = 0; i < 8; i++) l_i[i] = 0.f;
#pragma unroll
    for (int ip = 0; ip < 4; ip++)
#pragma unroll
        for (int j = 0; j < 4; j++) o2[ip][j] = 0ull;

    // This thread's 4 strided key columns: k = tx + 16j
    const float* ksrow0 = KsPs + tx * SK;           // + j*16*SK
    const int kslot0 = tx;                          // + 16j

    for (int k0 = 0; k0 < cnt_b; k0 += 64) {
        __syncthreads();  // prior GEMM2 done with Ps/Vs; iter0 covers Qt stores
        // K and V tiles, natural [k][d] layout, conflict-free float4 stores
#pragma unroll
        for (int r = 0; r < 4; r++) {
            int v = tid + r * 256;
            int row = v >> 4;
            int d4 = (v & 15) << 2;
            int slot = k0 + row;
            size_t gr = (size_t)(slot < cnt_b ? slot : cnt_b - 1) * HD_;
            *(float4*)(&KsPs[row * SK + d4]) = *(const float4*)(Kbase + gr + d4);
            *(float4*)(&Vs[row * SK + d4])   = *(const float4*)(Vbase + gr + d4);
        }
        __syncthreads();

        // GEMM1: S[128q x 64k] = Qs @ K^T. B-operand as float2 per 2 d-steps
        // (LDS.64: 16 distinct 8B segs = 128B = 1 wavefront, half the LDS.32
        // traffic). A-operand broadcast LDS.128 from Qt.
        uint64_t s2[4][4];
#pragma unroll
        for (int ip = 0; ip < 4; ip++)
#pragma unroll
            for (int j = 0; j < 4; j++) s2[ip][j] = 0ull;
#pragma unroll 8
        for (int d0 = 0; d0 < 64; d0 += 2) {
            float2 kb0 = *(const float2*)(ksrow0 + d0);
            float2 kb1 = *(const float2*)(ksrow0 + 16 * SK + d0);
            float2 kb2 = *(const float2*)(ksrow0 + 32 * SK + d0);
            float2 kb3 = *(const float2*)(ksrow0 + 48 * SK + d0);
            {
                const ulonglong2* ap = (const ulonglong2*)(&Qt[d0 * SQ + ty * 8]);
                ulonglong2 A0 = ap[0], A1 = ap[1];
                uint64_t a2[4] = {A0.x, A0.y, A1.x, A1.y};
                uint64_t bd[4] = {dup2(kb0.x), dup2(kb1.x), dup2(kb2.x), dup2(kb3.x)};
#pragma unroll
                for (int ip = 0; ip < 4; ip++)
#pragma unroll
                    for (int j = 0; j < 4; j++)
                        s2[ip][j] = ffma2(a2[ip], bd[j], s2[ip][j]);
            }
            {
                const ulonglong2* ap = (const ulonglong2*)(&Qt[(d0 + 1) * SQ + ty * 8]);
                ulonglong2 A0 = ap[0], A1 = ap[1];
                uint64_t a2[4] = {A0.x, A0.y, A1.x, A1.y};
                uint64_t bd[4] = {dup2(kb0.y), dup2(kb1.y), dup2(kb2.y), dup2(kb3.y)};
#pragma unroll
                for (int ip = 0; ip < 4; ip++)
#pragma unroll
                    for (int j = 0; j < 4; j++)
                        s2[ip][j] = ffma2(a2[ip], bd[j], s2[ip][j]);
            }
        }

        float s[8][4];
#pragma unroll
        for (int ip = 0; ip < 4; ip++)
#pragma unroll
            for (int j = 0; j < 4; j++)
                unpack2(s2[ip][j], s[2 * ip][j], s[2 * ip + 1][j]);

        // exp; pad slots (last tile) contribute exactly 0
        const bool tail = (k0 + 64 > cnt_b);
#pragma unroll
        for (int j = 0; j < 4; j++) {
            bool pad = tail && (k0 + kslot0 + 16 * j >= cnt_b);
#pragma unroll
            for (int i = 0; i < 8; i++)
                s[i][j] = pad ? 0.f : __expf(s[i][j]);
        }
        // row sums (k spread over 16 tx lanes: xor 8,4,2,1)
#pragma unroll
        for (int i = 0; i < 8; i++) {
            float rs = (s[i][0] + s[i][1]) + (s[i][2] + s[i][3]);
#pragma unroll
            for (int off = 8; off > 0; off >>= 1)
                rs += __shfl_xor_sync(0xffffffffu, rs, off);
            l_i[i] += rs;
        }

        __syncthreads();  // all Ks reads done before Ps overwrites region
        // Ps[k][q] store: two STS.128 per key column (was 8 STS.32)
#pragma unroll
        for (int j = 0; j < 4; j++) {
            float* pr = KsPs + (kslot0 + 16 * j) * SQ + ty * 8;
            *(float4*)(pr)     = make_float4(s[0][j], s[1][j], s[2][j], s[3][j]);
            *(float4*)(pr + 4) = make_float4(s[4][j], s[5][j], s[6][j], s[7][j]);
        }
        __syncthreads();

        // GEMM2: O += P @ V (A broadcast by ty; B float4 conflict-free)
#pragma unroll 8
        for (int k = 0; k < 64; k++) {
            const ulonglong2* pp = (const ulonglong2*)(&KsPs[k * SQ + ty * 8]);
            ulonglong2 P0 = pp[0], P1 = pp[1];
            uint64_t a2[4] = {P0.x, P0.y, P1.x, P1.y};
            float4 vv = *(const float4*)(&Vs[k * SK + tx * 4]);
            uint64_t bd[4] = {dup2(vv.x), dup2(vv.y), dup2(vv.z), dup2(vv.w)};
#pragma unroll
            for (int ip = 0; ip < 4; ip++)
#pragma unroll
                for (int j = 0; j < 4; j++)
                    o2[ip][j] = ffma2(a2[ip], bd[j], o2[ip][j]);
        }
    }

    // Epilogue
    float* Obase = Out + ((size_t)b * NQ_ + q0) * HD_ + h * D_;
#pragma unroll
    for (int ip = 0; ip < 4; ip++) {
        float lo[4], hi[4];
#pragma unroll
        for (int j = 0; j < 4; j++) unpack2(o2[ip][j], lo[j], hi[j]);
        float inv0 = 1.f / l_i[2 * ip];
        float inv1 = 1.f / l_i[2 * ip + 1];
        *(float4*)(Obase + (size_t)(ty * 8 + 2 * ip) * HD_ + tx * 4) =
            make_float4(lo[0] * inv0, lo[1] * inv0, lo[2] * inv0, lo[3] * inv0);
        *(float4*)(Obase + (size_t)(ty * 8 + 2 * ip + 1) * HD_ + tx * 4) =
            make_float4(hi[0] * inv1, hi[1] * inv1, hi[2] * inv1, hi[3] * inv1);
    }
}

// ---------------------------------------------------------------------------
// Launch. Graph-capturable: kernel launches only.
// ---------------------------------------------------------------------------
extern "C" void kernel_launch(void* const* d_in, const int* in_sizes, int n_in,
                              void* d_out, int out_size)
{
    (void)in_sizes; (void)n_in; (void)out_size;
    const float* query = (const float*)d_in[0];
    const float* key   = (const float*)d_in[1];
    const float* cmask = (const float*)d_in[2];
    const float* Wq    = (const float*)d_in[3];
    const float* bq    = (const float*)d_in[4];
    const float* Wk    = (const float*)d_in[5];
    const float* bk    = (const float*)d_in[6];
    const float* Wv    = (const float*)d_in[7];
    const float* bv    = (const float*)d_in[8];
    float* out = (float*)d_out;

    float *qbuf, *kbuf, *vbuf; int *ibuf, *cbuf;
    cudaGetSymbolAddress((void**)&qbuf, g_Q);
    cudaGetSymbolAddress((void**)&kbuf, g_K);
    cudaGetSymbolAddress((void**)&vbuf, g_V);
    cudaGetSymbolAddress((void**)&ibuf, g_idx);
    cudaGetSymbolAddress((void**)&cbuf, g_cnt);

    dim3 blk(256);
    compact_mask<<<B_, blk>>>(cmask, ibuf, cbuf);
    proj_gemm<<<dim3(64, 8), blk>>>(query, Wq, bq, qbuf);
    // 128 tiles cover B*NK; tiles past cnt[b] early-exit
    proj_kv<<<dim3(128, 8), blk>>>(key, Wk, bk, Wv, bv, ibuf, cbuf, kbuf, vbuf);

    cudaFuncSetAttribute(attn_kernel,
                         cudaFuncAttributeMaxDynamicSharedMemorySize,
                         ATTN_SMEM_BYTES);
    attn_kernel<<<dim3(NQ_ / 128, H_, B_), blk, ATTN_SMEM_BYTES>>>(
        qbuf, kbuf, vbuf, cbuf, out);
}